// round 1
// baseline (speedup 1.0000x reference)
#include <cuda_runtime.h>
#include <math.h>

#define BB 256
#define TT 20
#define DD 128
#define HH 256
#define KSZ 256
#define MEMN 20
#define YY 4
#define EPSF 1e-8f
#define NFRM (BB*TT)

// ---------------- device scratch (no allocations allowed) ----------------
__device__ float g_h3[NFRM*512];
__device__ float g_fc1[NFRM*256];
__device__ float g_z[NFRM*DD];
__device__ float g_X[BB*640];
__device__ float g_gates[BB*1024];
__device__ float g_gates2[BB*1024];
__device__ float g_heads[BB*768];
__device__ float g_heads2[BB*768];
__device__ float g_hst[BB*HH];
__device__ float g_cst[BB*HH];
__device__ float g_r[BB*KSZ];
__device__ float g_M[BB*MEMN*KSZ];
__device__ float g_Wcat[1024*640];
__device__ float g_Whead[768*256];

__device__ __forceinline__ float sigmf(float x){ return 1.f/(1.f+expf(-x)); }

// ---------------- fused conv encoder: one frame per block ----------------
// smem layout (floats):
// s_in  [34*34]      = 1156     zero-padded 32x32 input
// s_h1  [32*18*20]   = 11520    conv1 out, padded rows 18, row stride 20
// s_h2  [32*10*12]   = 3840     conv2 out, padded rows 10, row stride 12
// s_w1  [512], s_w2 [16384], s_w3 [16384]
#define S_IN 0
#define S_H1 1156
#define S_H2 12676
#define S_W1 16516
#define S_W2 17028
#define S_W3 33412
#define CONV_SMEM_FLOATS 49796

__global__ void __launch_bounds__(256) k_conv(
    const float* __restrict__ x,
    const float* __restrict__ w1, const float* __restrict__ b1,
    const float* __restrict__ w2, const float* __restrict__ b2,
    const float* __restrict__ w3, const float* __restrict__ b3)
{
    extern __shared__ float sm[];
    float* s_in = sm + S_IN;
    float* s_h1 = sm + S_H1;
    float* s_h2 = sm + S_H2;
    float* s_w1 = sm + S_W1;
    float* s_w2 = sm + S_W2;
    float* s_w3 = sm + S_W3;
    const int f   = blockIdx.x;
    const int tid = threadIdx.x;

    // zero padded activation buffers (contiguous region), load weights
    for (int i = tid; i < 16516; i += 256) sm[i] = 0.f;
    for (int i = tid; i < 512;   i += 256) s_w1[i] = w1[i];
    for (int i = tid; i < 16384; i += 256) { s_w2[i] = w2[i]; s_w3[i] = w3[i]; }
    __syncthreads();
    // stage input interior
    for (int i = tid; i < 1024; i += 256) {
        int iy = i >> 5, ix = i & 31;
        s_in[(iy+1)*34 + ix + 1] = x[f*1024 + i];
    }
    __syncthreads();

    // ---- conv1: 1->32ch, 4x4 s2 p1, 32x32 -> 16x16 ----
    for (int p = tid; p < 32*16; p += 256) {
        int oc = p >> 4, oy = p & 15;
        float bias = b1[oc];
        float acc[16];
        #pragma unroll
        for (int ox = 0; ox < 16; ox++) acc[ox] = bias;
        #pragma unroll
        for (int kh = 0; kh < 4; kh++) {
            const float* row = s_in + (2*oy+kh)*34;
            const float4 w = *(const float4*)(s_w1 + oc*16 + kh*4);
            #pragma unroll
            for (int ox = 0; ox < 16; ox++) {
                acc[ox] += row[2*ox]*w.x + row[2*ox+1]*w.y
                         + row[2*ox+2]*w.z + row[2*ox+3]*w.w;
            }
        }
        float* dst = s_h1 + oc*360 + (oy+1)*20 + 1;
        #pragma unroll
        for (int ox = 0; ox < 16; ox++) dst[ox] = fmaxf(acc[ox], 0.f);
    }
    __syncthreads();

    // ---- conv2: 32->32ch, 16x16 -> 8x8 (each thread: one (oc,oy) row) ----
    {
        int oc = tid >> 3, oy = tid & 7;
        float bias = b2[oc];
        float acc[8];
        #pragma unroll
        for (int ox = 0; ox < 8; ox++) acc[ox] = bias;
        for (int ic = 0; ic < 32; ic++) {
            const float* chan = s_h1 + ic*360;
            #pragma unroll
            for (int kh = 0; kh < 4; kh++) {
                const float* row = chan + (2*oy+kh)*20;
                float4 r0 = *(const float4*)(row);
                float4 r1 = *(const float4*)(row+4);
                float4 r2 = *(const float4*)(row+8);
                float4 r3 = *(const float4*)(row+12);
                float2 r4 = *(const float2*)(row+16);
                float rr[18] = {r0.x,r0.y,r0.z,r0.w, r1.x,r1.y,r1.z,r1.w,
                                r2.x,r2.y,r2.z,r2.w, r3.x,r3.y,r3.z,r3.w,
                                r4.x,r4.y};
                const float4 w = *(const float4*)(s_w2 + oc*512 + ic*16 + kh*4);
                #pragma unroll
                for (int ox = 0; ox < 8; ox++) {
                    acc[ox] += rr[2*ox]*w.x + rr[2*ox+1]*w.y
                             + rr[2*ox+2]*w.z + rr[2*ox+3]*w.w;
                }
            }
        }
        float* dst = s_h2 + oc*120 + (oy+1)*12 + 1;
        #pragma unroll
        for (int ox = 0; ox < 8; ox++) dst[ox] = fmaxf(acc[ox], 0.f);
    }
    __syncthreads();

    // ---- conv3: 32->32ch, 8x8 -> 4x4 (each thread: 2 adjacent ox) ----
    {
        int oc = tid >> 3, oy = (tid >> 1) & 3, q = tid & 1;
        float bias = b3[oc];
        float acc0 = bias, acc1 = bias;
        for (int ic = 0; ic < 32; ic++) {
            const float* chan = s_h2 + ic*120;
            #pragma unroll
            for (int kh = 0; kh < 4; kh++) {
                const float* row = chan + (2*oy+kh)*12 + 4*q;
                float4 a = *(const float4*)(row);
                float4 b = *(const float4*)(row+4);
                const float4 w = *(const float4*)(s_w3 + oc*512 + ic*16 + kh*4);
                acc0 += a.x*w.x + a.y*w.y + a.z*w.z + a.w*w.w;
                acc1 += a.z*w.x + a.w*w.y + b.x*w.z + b.y*w.w;
            }
        }
        int base = f*512 + oc*16 + oy*4 + 2*q;
        g_h3[base]   = fmaxf(acc0, 0.f);
        g_h3[base+1] = fmaxf(acc1, 0.f);
    }
}

// ---------------- generic fp32 GEMM: C = act(A @ W^T + bias) ----------------
// 64x64 tile, BK=16, 256 threads, 4x4 per thread. blockIdx.z==1 -> split-K
// second half (A+kOff, W+kOff) into Calt without bias (summed by consumer).
__global__ void __launch_bounds__(256) k_gemm(
    const float* __restrict__ A, int lda,
    const float* __restrict__ W, int ldw,
    const float* __restrict__ bias,
    float* __restrict__ C, float* __restrict__ Calt,
    int ldc, int K, int kOff, int act)
{
    __shared__ float sA[16][68];
    __shared__ float sW[16][68];
    const float* Ap = A;
    const float* Wp = W;
    float* Cp = C;
    const float* bp = bias;
    if (blockIdx.z == 1) { Ap += kOff; Wp += kOff; Cp = Calt; bp = nullptr; }

    int tid = threadIdx.x;
    int tx = tid & 15, ty = tid >> 4;
    int lr = tid >> 2;
    int lk = (tid & 3) << 2;
    const float* Ab = Ap + (blockIdx.y*64 + lr)*lda + lk;
    const float* Wb = Wp + (blockIdx.x*64 + lr)*ldw + lk;

    float acc[4][4];
    #pragma unroll
    for (int i = 0; i < 4; i++)
        #pragma unroll
        for (int j = 0; j < 4; j++) acc[i][j] = 0.f;

    for (int k0 = 0; k0 < K; k0 += 16) {
        float4 a4 = *(const float4*)(Ab + k0);
        float4 w4 = *(const float4*)(Wb + k0);
        sA[lk+0][lr] = a4.x; sA[lk+1][lr] = a4.y; sA[lk+2][lr] = a4.z; sA[lk+3][lr] = a4.w;
        sW[lk+0][lr] = w4.x; sW[lk+1][lr] = w4.y; sW[lk+2][lr] = w4.z; sW[lk+3][lr] = w4.w;
        __syncthreads();
        #pragma unroll
        for (int kk = 0; kk < 16; kk++) {
            float4 av = *(const float4*)&sA[kk][ty<<2];
            float4 wv = *(const float4*)&sW[kk][tx<<2];
            float a[4] = {av.x, av.y, av.z, av.w};
            float w[4] = {wv.x, wv.y, wv.z, wv.w};
            #pragma unroll
            for (int i = 0; i < 4; i++)
                #pragma unroll
                for (int j = 0; j < 4; j++) acc[i][j] += a[i]*w[j];
        }
        __syncthreads();
    }
    int rb = blockIdx.y*64 + (ty<<2);
    int cb = blockIdx.x*64 + (tx<<2);
    #pragma unroll
    for (int i = 0; i < 4; i++) {
        #pragma unroll
        for (int j = 0; j < 4; j++) {
            float v = acc[i][j];
            if (bp) v += bp[cb+j];
            if (act == 1) v = fmaxf(v, 0.f);
            Cp[(rb+i)*ldc + cb + j] = v;
        }
    }
}

// ---------------- context norm over time (unbiased var) ----------------
__global__ void k_ctxnorm(const float* __restrict__ gamma, const float* __restrict__ beta)
{
    int b = blockIdx.x, d = threadIdx.x;   // 128 threads
    float v[TT];
    float s = 0.f, s2 = 0.f;
    #pragma unroll
    for (int t = 0; t < TT; t++) {
        v[t] = g_z[(b*TT+t)*DD + d];
        s += v[t]; s2 += v[t]*v[t];
    }
    float mu  = s / TT;
    float var = (s2 - TT*mu*mu) / (TT - 1);
    float inv = 1.f / sqrtf(var + EPSF);
    float ga = gamma[d], be = beta[d];
    #pragma unroll
    for (int t = 0; t < TT; t++)
        g_z[(b*TT+t)*DD + d] = (v[t] - mu)*inv*ga + be;
}

// ---------------- state init + weight concat builders ----------------
__global__ void k_init(const float* __restrict__ mem0)
{
    int i = blockIdx.x*256 + threadIdx.x;
    if (i < BB*MEMN*KSZ) g_M[i] = mem0[i % (MEMN*KSZ)];
    if (i < BB*HH) { g_hst[i] = 0.f; g_cst[i] = 0.f; }
    if (i < BB*KSZ) g_r[i] = 0.f;
}
__global__ void k_build_wcat(const float* __restrict__ wi, const float* __restrict__ wh)
{
    int i = blockIdx.x*256 + threadIdx.x;
    if (i >= 1024*640) return;
    int j = i / 640, c = i - j*640;
    g_Wcat[i] = (c < 384) ? wi[j*384 + c] : wh[j*256 + (c-384)];
}
__global__ void k_build_whead(const float* __restrict__ wk, const float* __restrict__ wwk,
                              const float* __restrict__ wv)
{
    int i = blockIdx.x*256 + threadIdx.x;
    if (i >= 768*256) return;
    int n = i >> 8;
    g_Whead[i] = (n < 256) ? wk[i] : ((n < 512) ? wwk[i - 256*256] : wv[i - 512*256]);
}
__global__ void k_zero_out(float* __restrict__ out, int n)
{
    int i = blockIdx.x*256 + threadIdx.x;
    if (i < n) out[i] = 0.f;
}

// ---------------- per-step: pack X = [z_t, r, h] ----------------
__global__ void k_pack(int t)
{
    int i = blockIdx.x*256 + threadIdx.x;   // BB*640
    int b = i / 640, c = i - b*640;
    float v;
    if (c < DD)            v = g_z[(b*TT+t)*DD + c];
    else if (c < DD+KSZ)   v = g_r[b*KSZ + (c - DD)];
    else                   v = g_hst[b*HH + (c - DD - KSZ)];
    g_X[i] = v;
}

// ---------------- per-step: LSTM elementwise update ----------------
__global__ void k_lstm()
{
    int i = blockIdx.x*256 + threadIdx.x;   // BB*HH
    int b = i >> 8, j = i & 255;
    const float* g1 = g_gates  + b*1024;
    const float* g2 = g_gates2 + b*1024;
    float ig = g1[j]       + g2[j];
    float fg = g1[256 + j] + g2[256 + j];
    float gg = g1[512 + j] + g2[512 + j];
    float og = g1[768 + j] + g2[768 + j];
    float c = sigmf(fg)*g_cst[i] + sigmf(ig)*tanhf(gg);
    float h = sigmf(og)*tanhf(c);
    g_cst[i] = c;
    g_hst[i] = h;
}

// ---------------- per-step: memory read/write + (last step) output ----------------
__global__ void __launch_bounds__(256) k_mem(int t, const float* __restrict__ wo,
                                             const float* __restrict__ wob,
                                             float* __restrict__ out, int out_size)
{
    __shared__ float s_kr[256], s_kw[256], s_v[256], s_rnew[256];
    __shared__ float s_simr[MEMN], s_simw[MEMN];
    __shared__ float s_wr[4], s_ws[4];
    __shared__ int   s_ir[4], s_iw[4];
    __shared__ float s_red[16];
    __shared__ float s_nrm[2];
    __shared__ float s_y[4];

    int b = blockIdx.x, tid = threadIdx.x;
    int lane = tid & 31, wid = tid >> 5;
    const float* hd1 = g_heads  + b*768;
    const float* hd2 = g_heads2 + b*768;

    float kr = hd1[tid]       + hd2[tid];
    float kw = hd1[256 + tid] + hd2[256 + tid];
    s_kr[tid] = kr;
    s_kw[tid] = kw;
    s_v[tid]  = tanhf(hd1[512 + tid] + hd2[512 + tid]);

    // |kq| norms (block reduce of squares)
    float pr = kr*kr, pw = kw*kw;
    #pragma unroll
    for (int o = 16; o > 0; o >>= 1) {
        pr += __shfl_xor_sync(0xffffffffu, pr, o);
        pw += __shfl_xor_sync(0xffffffffu, pw, o);
    }
    if (lane == 0) { s_red[wid] = pr; s_red[8 + wid] = pw; }
    __syncthreads();
    if (tid == 0) {
        float sr = 0.f, sw = 0.f;
        #pragma unroll
        for (int w = 0; w < 8; w++) { sr += s_red[w]; sw += s_red[8 + w]; }
        s_nrm[0] = sqrtf(sr) + EPSF;
        s_nrm[1] = sqrtf(sw) + EPSF;
    }
    __syncthreads();

    // cosine sims vs all memory rows (one warp per row, round-robin)
    for (int n = wid; n < MEMN; n += 8) {
        const float* Mr = g_M + (b*MEMN + n)*KSZ;
        float dr = 0.f, dw = 0.f, nn = 0.f;
        #pragma unroll
        for (int d0 = 0; d0 < KSZ; d0 += 32) {
            float m = Mr[d0 + lane];
            dr += s_kr[d0 + lane]*m;
            dw += s_kw[d0 + lane]*m;
            nn += m*m;
        }
        #pragma unroll
        for (int o = 16; o > 0; o >>= 1) {
            dr += __shfl_xor_sync(0xffffffffu, dr, o);
            dw += __shfl_xor_sync(0xffffffffu, dw, o);
            nn += __shfl_xor_sync(0xffffffffu, nn, o);
        }
        if (lane == 0) {
            float mn = sqrtf(nn) + EPSF;
            s_simr[n] = dr / (s_nrm[0]*mn);
            s_simw[n] = dw / (s_nrm[1]*mn);
        }
    }
    __syncthreads();

    // top-4 (stable, lowest index on ties) + softmax; thread0=read, thread1=write
    if (tid < 2) {
        const float* sims = tid ? s_simw : s_simr;
        float* wout = tid ? s_ws : s_wr;
        int*   iout = tid ? s_iw : s_ir;
        unsigned used = 0;
        float vals[4];
        #pragma unroll
        for (int k = 0; k < 4; k++) {
            float best = -1e30f; int bi = 0;
            for (int n = 0; n < MEMN; n++) {
                if (!((used >> n) & 1u) && sims[n] > best) { best = sims[n]; bi = n; }
            }
            used |= 1u << bi;
            iout[k] = bi; vals[k] = best;
        }
        float mx = vals[0], ssum = 0.f, e[4];
        #pragma unroll
        for (int k = 0; k < 4; k++) { e[k] = expf(vals[k] - mx); ssum += e[k]; }
        #pragma unroll
        for (int k = 0; k < 4; k++) wout[k] = e[k] / ssum;
    }
    __syncthreads();

    // read (pre-write M) — each thread owns column `tid` for both read & write
    float r = 0.f;
    #pragma unroll
    for (int k = 0; k < 4; k++)
        r += s_wr[k] * g_M[(b*MEMN + s_ir[k])*KSZ + tid];
    g_r[b*KSZ + tid] = r;
    s_rnew[tid] = r;

    // scatter-add write (top-k indices are distinct; columns disjoint per thread)
    float vv = s_v[tid];
    #pragma unroll
    for (int k = 0; k < 4; k++)
        g_M[(b*MEMN + s_iw[k])*KSZ + tid] += s_ws[k] * vv;

    if (t == TT - 1) {
        __syncthreads();
        if (wid < 4) {
            const float* wrow = wo + wid*512;
            float p = 0.f;
            for (int j = lane; j < 256; j += 32) p += wrow[j]       * g_hst[b*HH + j];
            for (int j = lane; j < 256; j += 32) p += wrow[256 + j] * s_rnew[j];
            #pragma unroll
            for (int o = 16; o > 0; o >>= 1) p += __shfl_xor_sync(0xffffffffu, p, o);
            if (lane == 0) s_y[wid] = p + wob[wid];
        }
        __syncthreads();
        if (tid < 4 && (b*4 + tid) < out_size) out[b*4 + tid] = s_y[tid];
        if (tid == 0 && out_size >= BB*YY + BB) {
            int am = 0; float bv = s_y[0];
            #pragma unroll
            for (int o = 1; o < 4; o++) if (s_y[o] > bv) { bv = s_y[o]; am = o; }
            out[BB*YY + b] = (float)am;
        }
    }
}

// ---------------- launch ----------------
extern "C" void kernel_launch(void* const* d_in, const int* in_sizes, int n_in,
                              void* d_out, int out_size)
{
    const float* x    = (const float*)d_in[0];
    const float* c1w  = (const float*)d_in[1];
    const float* c1b  = (const float*)d_in[2];
    const float* c2w  = (const float*)d_in[3];
    const float* c2b  = (const float*)d_in[4];
    const float* c3w  = (const float*)d_in[5];
    const float* c3b  = (const float*)d_in[6];
    const float* fc1w = (const float*)d_in[7];
    const float* fc1b = (const float*)d_in[8];
    const float* fc2w = (const float*)d_in[9];
    const float* fc2b = (const float*)d_in[10];
    const float* gamma= (const float*)d_in[11];
    const float* beta = (const float*)d_in[12];
    const float* lwi  = (const float*)d_in[13];
    const float* lwh  = (const float*)d_in[14];
    const float* lb   = (const float*)d_in[15];
    const float* wk   = (const float*)d_in[16];
    const float* wwk  = (const float*)d_in[17];
    const float* wv   = (const float*)d_in[18];
    const float* wo   = (const float*)d_in[19];
    const float* wob  = (const float*)d_in[20];
    const float* mem0 = (const float*)d_in[21];
    float* out = (float*)d_out;

    cudaFuncSetAttribute(k_conv, cudaFuncAttributeMaxDynamicSharedMemorySize,
                         CONV_SMEM_FLOATS * 4);

    float *p_h3, *p_fc1, *p_z, *p_X, *p_g1, *p_g2, *p_hd1, *p_hd2, *p_h, *p_wcat, *p_whead;
    cudaGetSymbolAddress((void**)&p_h3,    g_h3);
    cudaGetSymbolAddress((void**)&p_fc1,   g_fc1);
    cudaGetSymbolAddress((void**)&p_z,     g_z);
    cudaGetSymbolAddress((void**)&p_X,     g_X);
    cudaGetSymbolAddress((void**)&p_g1,    g_gates);
    cudaGetSymbolAddress((void**)&p_g2,    g_gates2);
    cudaGetSymbolAddress((void**)&p_hd1,   g_heads);
    cudaGetSymbolAddress((void**)&p_hd2,   g_heads2);
    cudaGetSymbolAddress((void**)&p_h,     g_hst);
    cudaGetSymbolAddress((void**)&p_wcat,  g_Wcat);
    cudaGetSymbolAddress((void**)&p_whead, g_Whead);

    if (out_size > 0)
        k_zero_out<<<(out_size + 255)/256, 256>>>(out, out_size);

    // encoder
    k_conv<<<NFRM, 256, CONV_SMEM_FLOATS * 4>>>(x, c1w, c1b, c2w, c2b, c3w, c3b);
    // fc1: [5120,512] @ [256,512]^T -> relu
    k_gemm<<<dim3(4, 80, 1), 256>>>(p_h3, 512, fc1w, 512, fc1b, p_fc1, nullptr, 256, 512, 0, 1);
    // fc2: [5120,256] @ [128,256]^T -> relu
    k_gemm<<<dim3(2, 80, 1), 256>>>(p_fc1, 256, fc2w, 256, fc2b, p_z, nullptr, 128, 256, 0, 1);
    // context norm over time
    k_ctxnorm<<<BB, 128>>>(gamma, beta);

    // recurrence setup
    k_init<<<(BB*MEMN*KSZ + 255)/256, 256>>>(mem0);
    k_build_wcat<<<(1024*640 + 255)/256, 256>>>(lwi, lwh);
    k_build_whead<<<(768*256 + 255)/256, 256>>>(wk, wwk, wv);

    for (int t = 0; t < TT; t++) {
        k_pack<<<BB*640/256, 256>>>(t);
        // gates: [256,640] @ [1024,640]^T + b (split-K x2 via blockIdx.z)
        k_gemm<<<dim3(16, 4, 2), 256>>>(p_X, 640, p_wcat, 640, lb,
                                        p_g1, p_g2, 1024, 320, 320, 0);
        k_lstm<<<BB*HH/256, 256>>>();
        // heads: [256,256] @ [768,256]^T (split-K x2)
        k_gemm<<<dim3(12, 4, 2), 256>>>(p_h, 256, p_whead, 256, nullptr,
                                        p_hd1, p_hd2, 768, 128, 128, 0);
        k_mem<<<BB, 256>>>(t, wo, wob, out, out_size);
    }
}

// round 2
// speedup vs baseline: 1.1863x; 1.1863x over previous
#include <cuda_runtime.h>
#include <math.h>

#define BB 256
#define TT 20
#define DD 128
#define HH 256
#define KSZ 256
#define MEMN 20
#define YY 4
#define EPSF 1e-8f
#define NFRM (BB*TT)

// ---------------- device scratch (no allocations allowed) ----------------
__device__ float g_h3[NFRM*512];
__device__ float g_fc1[NFRM*256];
__device__ float g_z[NFRM*DD];
__device__ float g_gates[BB*1024];
__device__ float g_gates2[BB*1024];
__device__ float g_heads[BB*768];
__device__ float g_heads2[BB*768];
__device__ float g_hst[BB*HH];
__device__ float g_cst[BB*HH];
__device__ float g_r[BB*KSZ];
__device__ float g_M[BB*MEMN*KSZ];
__device__ float g_Wcat[1024*640];
__device__ float g_Whead[768*256];

__device__ __forceinline__ float sigmf(float x){ return 1.f/(1.f+expf(-x)); }

// ---------------- fused conv encoder: one frame per block ----------------
// smem (floats): s_in [34*34]=1156, s_h1 [32*18*20]=11520, s_h2 [32*10*12]=3840
// weights read straight through L1 (warp-uniform broadcast, L1-resident).
#define S_IN 0
#define S_H1 1156
#define S_H2 12676
#define CONV_SMEM_FLOATS 16516

__global__ void __launch_bounds__(256, 3) k_conv(
    const float* __restrict__ x,
    const float* __restrict__ w1, const float* __restrict__ b1,
    const float* __restrict__ w2, const float* __restrict__ b2,
    const float* __restrict__ w3, const float* __restrict__ b3)
{
    extern __shared__ float sm[];
    float* s_in = sm + S_IN;
    float* s_h1 = sm + S_H1;
    float* s_h2 = sm + S_H2;
    const int f   = blockIdx.x;
    const int tid = threadIdx.x;

    for (int i = tid; i < CONV_SMEM_FLOATS; i += 256) sm[i] = 0.f;
    __syncthreads();
    for (int i = tid; i < 1024; i += 256) {
        int iy = i >> 5, ix = i & 31;
        s_in[(iy+1)*34 + ix + 1] = x[f*1024 + i];
    }
    __syncthreads();

    // ---- conv1: 1->32ch, 4x4 s2 p1, 32x32 -> 16x16 ----
    for (int p = tid; p < 32*16; p += 256) {
        int oc = p >> 4, oy = p & 15;
        float bias = __ldg(b1 + oc);
        float acc[16];
        #pragma unroll
        for (int ox = 0; ox < 16; ox++) acc[ox] = bias;
        #pragma unroll
        for (int kh = 0; kh < 4; kh++) {
            const float* row = s_in + (2*oy+kh)*34;
            const float4 w = __ldg((const float4*)(w1 + oc*16 + kh*4));
            #pragma unroll
            for (int ox = 0; ox < 16; ox++) {
                acc[ox] += row[2*ox]*w.x + row[2*ox+1]*w.y
                         + row[2*ox+2]*w.z + row[2*ox+3]*w.w;
            }
        }
        float* dst = s_h1 + oc*360 + (oy+1)*20 + 1;
        #pragma unroll
        for (int ox = 0; ox < 16; ox++) dst[ox] = fmaxf(acc[ox], 0.f);
    }
    __syncthreads();

    // ---- conv2: 32->32ch, 16x16 -> 8x8 (thread = one (oc,oy) row) ----
    {
        int oc = tid >> 3, oy = tid & 7;
        float bias = __ldg(b2 + oc);
        float acc[8];
        #pragma unroll
        for (int ox = 0; ox < 8; ox++) acc[ox] = bias;
        for (int ic = 0; ic < 32; ic++) {
            const float* chan = s_h1 + ic*360;
            #pragma unroll
            for (int kh = 0; kh < 4; kh++) {
                const float* row = chan + (2*oy+kh)*20;
                float4 r0 = *(const float4*)(row);
                float4 r1 = *(const float4*)(row+4);
                float4 r2 = *(const float4*)(row+8);
                float4 r3 = *(const float4*)(row+12);
                float2 r4 = *(const float2*)(row+16);
                float rr[18] = {r0.x,r0.y,r0.z,r0.w, r1.x,r1.y,r1.z,r1.w,
                                r2.x,r2.y,r2.z,r2.w, r3.x,r3.y,r3.z,r3.w,
                                r4.x,r4.y};
                const float4 w = __ldg((const float4*)(w2 + oc*512 + ic*16 + kh*4));
                #pragma unroll
                for (int ox = 0; ox < 8; ox++) {
                    acc[ox] += rr[2*ox]*w.x + rr[2*ox+1]*w.y
                             + rr[2*ox+2]*w.z + rr[2*ox+3]*w.w;
                }
            }
        }
        float* dst = s_h2 + oc*120 + (oy+1)*12 + 1;
        #pragma unroll
        for (int ox = 0; ox < 8; ox++) dst[ox] = fmaxf(acc[ox], 0.f);
    }
    __syncthreads();

    // ---- conv3: 32->32ch, 8x8 -> 4x4 (thread = 2 adjacent ox) ----
    {
        int oc = tid >> 3, oy = (tid >> 1) & 3, q = tid & 1;
        float bias = __ldg(b3 + oc);
        float acc0 = bias, acc1 = bias;
        for (int ic = 0; ic < 32; ic++) {
            const float* chan = s_h2 + ic*120;
            #pragma unroll
            for (int kh = 0; kh < 4; kh++) {
                const float* row = chan + (2*oy+kh)*12 + 4*q;
                float4 a = *(const float4*)(row);
                float4 b = *(const float4*)(row+4);
                const float4 w = __ldg((const float4*)(w3 + oc*512 + ic*16 + kh*4));
                acc0 += a.x*w.x + a.y*w.y + a.z*w.z + a.w*w.w;
                acc1 += a.z*w.x + a.w*w.y + b.x*w.z + b.y*w.w;
            }
        }
        int base = f*512 + oc*16 + oy*4 + 2*q;
        g_h3[base]   = fmaxf(acc0, 0.f);
        g_h3[base+1] = fmaxf(acc1, 0.f);
    }
}

// ---------------- fp32 GEMM, double-buffered: C = act(A @ W^T + bias) ----------------
// 64x64 tile, BK=16, 256 threads, 4x4 per thread.
// mode 0: A is a plain matrix (lda). mode 1: A row b is [z(b,t,:), r(b,:), h(b,:)] (640 cols).
// blockIdx.z==1 -> split-K second half into Calt without bias.
__global__ void __launch_bounds__(256) k_gemm(
    const float* __restrict__ A, int lda,
    const float* __restrict__ W, int ldw,
    const float* __restrict__ bias,
    float* __restrict__ C, float* __restrict__ Calt,
    int ldc, int K, int kOff, int act, int mode, int t)
{
    __shared__ float sA[2][16][68];
    __shared__ float sW[2][16][68];
    const float* Wp = W;
    float* Cp = C;
    const float* bp = bias;
    int kBase = 0;
    if (blockIdx.z == 1) { kBase = kOff; Wp += kOff; Cp = Calt; bp = nullptr; }

    int tid = threadIdx.x;
    int tx = tid & 15, ty = tid >> 4;
    int lr = tid >> 2;
    int lk = (tid & 3) << 2;
    int rowA = blockIdx.y*64 + lr;
    const float* Ab = (mode == 0) ? (A + rowA*lda + kBase + lk) : nullptr;
    const float* Wb = Wp + (blockIdx.x*64 + lr)*ldw + lk;

    float acc[4][4];
    #pragma unroll
    for (int i = 0; i < 4; i++)
        #pragma unroll
        for (int j = 0; j < 4; j++) acc[i][j] = 0.f;

    // A gather for mode 1 (X = [z_t | r | h])
    auto loadA = [&](int k0) -> float4 {
        if (mode == 0) return *(const float4*)(Ab + k0);
        int c = kBase + k0 + lk;
        if (c < DD)          return *(const float4*)(g_z + (rowA*TT + t)*DD + c);
        else if (c < DD+KSZ) return *(const float4*)(g_r + rowA*KSZ + (c - DD));
        else                 return *(const float4*)(g_hst + rowA*HH + (c - DD - KSZ));
    };

    int nk = K >> 4;
    float4 a4 = loadA(0);
    float4 w4 = *(const float4*)(Wb);
    sA[0][lk+0][lr] = a4.x; sA[0][lk+1][lr] = a4.y; sA[0][lk+2][lr] = a4.z; sA[0][lk+3][lr] = a4.w;
    sW[0][lk+0][lr] = w4.x; sW[0][lk+1][lr] = w4.y; sW[0][lk+2][lr] = w4.z; sW[0][lk+3][lr] = w4.w;
    __syncthreads();

    for (int kb = 0; kb < nk; kb++) {
        int s = kb & 1;
        float4 na, nw;
        if (kb + 1 < nk) {
            na = loadA((kb+1) << 4);
            nw = *(const float4*)(Wb + ((kb+1) << 4));
        }
        #pragma unroll
        for (int kk = 0; kk < 16; kk++) {
            float4 av = *(const float4*)&sA[s][kk][ty<<2];
            float4 wv = *(const float4*)&sW[s][kk][tx<<2];
            float a[4] = {av.x, av.y, av.z, av.w};
            float w[4] = {wv.x, wv.y, wv.z, wv.w};
            #pragma unroll
            for (int i = 0; i < 4; i++)
                #pragma unroll
                for (int j = 0; j < 4; j++) acc[i][j] += a[i]*w[j];
        }
        if (kb + 1 < nk) {
            int d = s ^ 1;
            sA[d][lk+0][lr] = na.x; sA[d][lk+1][lr] = na.y; sA[d][lk+2][lr] = na.z; sA[d][lk+3][lr] = na.w;
            sW[d][lk+0][lr] = nw.x; sW[d][lk+1][lr] = nw.y; sW[d][lk+2][lr] = nw.z; sW[d][lk+3][lr] = nw.w;
            __syncthreads();
        }
    }

    int rb = blockIdx.y*64 + (ty<<2);
    int cb = blockIdx.x*64 + (tx<<2);
    #pragma unroll
    for (int i = 0; i < 4; i++) {
        #pragma unroll
        for (int j = 0; j < 4; j++) {
            float v = acc[i][j];
            if (bp) v += bp[cb+j];
            if (act == 1) v = fmaxf(v, 0.f);
            Cp[(rb+i)*ldc + cb + j] = v;
        }
    }
}

// ---------------- context norm over time (unbiased var) ----------------
__global__ void k_ctxnorm(const float* __restrict__ gamma, const float* __restrict__ beta)
{
    int b = blockIdx.x, d = threadIdx.x;   // 128 threads
    float v[TT];
    float s = 0.f, s2 = 0.f;
    #pragma unroll
    for (int t = 0; t < TT; t++) {
        v[t] = g_z[(b*TT+t)*DD + d];
        s += v[t]; s2 += v[t]*v[t];
    }
    float mu  = s / TT;
    float var = (s2 - TT*mu*mu) / (TT - 1);
    float inv = 1.f / sqrtf(var + EPSF);
    float ga = gamma[d], be = beta[d];
    #pragma unroll
    for (int t = 0; t < TT; t++)
        g_z[(b*TT+t)*DD + d] = (v[t] - mu)*inv*ga + be;
}

// ---------------- combined setup: state init + weight concat + out zero ----------------
__global__ void k_setup(const float* __restrict__ mem0,
                        const float* __restrict__ wi, const float* __restrict__ wh,
                        const float* __restrict__ wk, const float* __restrict__ wwk,
                        const float* __restrict__ wv,
                        float* __restrict__ out, int out_size)
{
    int i = blockIdx.x*256 + threadIdx.x;
    if (i < BB*MEMN*KSZ) g_M[i] = mem0[i % (MEMN*KSZ)];
    if (i < 1024*640) {
        int j = i / 640, c = i - j*640;
        g_Wcat[i] = (c < 384) ? wi[j*384 + c] : wh[j*256 + (c-384)];
    }
    if (i < 768*256) {
        int n = i >> 8;
        g_Whead[i] = (n < 256) ? wk[i] : ((n < 512) ? wwk[i - 256*256] : wv[i - 512*256]);
    }
    if (i < BB*HH) { g_hst[i] = 0.f; g_cst[i] = 0.f; }
    if (i < BB*KSZ) g_r[i] = 0.f;
    if (i < out_size) out[i] = 0.f;
}

// ---------------- per-step: LSTM elementwise update ----------------
__global__ void k_lstm()
{
    int i = blockIdx.x*256 + threadIdx.x;   // BB*HH
    int b = i >> 8, j = i & 255;
    const float* g1 = g_gates  + b*1024;
    const float* g2 = g_gates2 + b*1024;
    float ig = g1[j]       + g2[j];
    float fg = g1[256 + j] + g2[256 + j];
    float gg = g1[512 + j] + g2[512 + j];
    float og = g1[768 + j] + g2[768 + j];
    float c = sigmf(fg)*g_cst[i] + sigmf(ig)*tanhf(gg);
    float h = sigmf(og)*tanhf(c);
    g_cst[i] = c;
    g_hst[i] = h;
}

// ---------------- per-step: memory read/write + (last step) output ----------------
__global__ void __launch_bounds__(256) k_mem(int t, const float* __restrict__ wo,
                                             const float* __restrict__ wob,
                                             float* __restrict__ out, int out_size)
{
    __shared__ float s_kr[256], s_kw[256], s_v[256], s_rnew[256];
    __shared__ float s_simr[MEMN], s_simw[MEMN];
    __shared__ float s_wr[4], s_ws[4];
    __shared__ int   s_ir[4], s_iw[4];
    __shared__ float s_red[16];
    __shared__ float s_nrm[2];
    __shared__ float s_y[4];

    int b = blockIdx.x, tid = threadIdx.x;
    int lane = tid & 31, wid = tid >> 5;
    const float* hd1 = g_heads  + b*768;
    const float* hd2 = g_heads2 + b*768;

    float kr = hd1[tid]       + hd2[tid];
    float kw = hd1[256 + tid] + hd2[256 + tid];
    s_kr[tid] = kr;
    s_kw[tid] = kw;
    s_v[tid]  = tanhf(hd1[512 + tid] + hd2[512 + tid]);

    float pr = kr*kr, pw = kw*kw;
    #pragma unroll
    for (int o = 16; o > 0; o >>= 1) {
        pr += __shfl_xor_sync(0xffffffffu, pr, o);
        pw += __shfl_xor_sync(0xffffffffu, pw, o);
    }
    if (lane == 0) { s_red[wid] = pr; s_red[8 + wid] = pw; }
    __syncthreads();
    if (tid == 0) {
        float sr = 0.f, sw = 0.f;
        #pragma unroll
        for (int w = 0; w < 8; w++) { sr += s_red[w]; sw += s_red[8 + w]; }
        s_nrm[0] = sqrtf(sr) + EPSF;
        s_nrm[1] = sqrtf(sw) + EPSF;
    }
    __syncthreads();

    for (int n = wid; n < MEMN; n += 8) {
        const float* Mr = g_M + (b*MEMN + n)*KSZ;
        float dr = 0.f, dw = 0.f, nn = 0.f;
        #pragma unroll
        for (int d0 = 0; d0 < KSZ; d0 += 32) {
            float m = Mr[d0 + lane];
            dr += s_kr[d0 + lane]*m;
            dw += s_kw[d0 + lane]*m;
            nn += m*m;
        }
        #pragma unroll
        for (int o = 16; o > 0; o >>= 1) {
            dr += __shfl_xor_sync(0xffffffffu, dr, o);
            dw += __shfl_xor_sync(0xffffffffu, dw, o);
            nn += __shfl_xor_sync(0xffffffffu, nn, o);
        }
        if (lane == 0) {
            float mn = sqrtf(nn) + EPSF;
            s_simr[n] = dr / (s_nrm[0]*mn);
            s_simw[n] = dw / (s_nrm[1]*mn);
        }
    }
    __syncthreads();

    if (tid < 2) {
        const float* sims = tid ? s_simw : s_simr;
        float* wout = tid ? s_ws : s_wr;
        int*   iout = tid ? s_iw : s_ir;
        unsigned used = 0;
        float vals[4];
        #pragma unroll
        for (int k = 0; k < 4; k++) {
            float best = -1e30f; int bi = 0;
            for (int n = 0; n < MEMN; n++) {
                if (!((used >> n) & 1u) && sims[n] > best) { best = sims[n]; bi = n; }
            }
            used |= 1u << bi;
            iout[k] = bi; vals[k] = best;
        }
        float mx = vals[0], ssum = 0.f, e[4];
        #pragma unroll
        for (int k = 0; k < 4; k++) { e[k] = expf(vals[k] - mx); ssum += e[k]; }
        #pragma unroll
        for (int k = 0; k < 4; k++) wout[k] = e[k] / ssum;
    }
    __syncthreads();

    float r = 0.f;
    #pragma unroll
    for (int k = 0; k < 4; k++)
        r += s_wr[k] * g_M[(b*MEMN + s_ir[k])*KSZ + tid];
    g_r[b*KSZ + tid] = r;
    s_rnew[tid] = r;

    float vv = s_v[tid];
    #pragma unroll
    for (int k = 0; k < 4; k++)
        g_M[(b*MEMN + s_iw[k])*KSZ + tid] += s_ws[k] * vv;

    if (t == TT - 1) {
        __syncthreads();
        if (wid < 4) {
            const float* wrow = wo + wid*512;
            float p = 0.f;
            for (int j = lane; j < 256; j += 32) p += wrow[j]       * g_hst[b*HH + j];
            for (int j = lane; j < 256; j += 32) p += wrow[256 + j] * s_rnew[j];
            #pragma unroll
            for (int o = 16; o > 0; o >>= 1) p += __shfl_xor_sync(0xffffffffu, p, o);
            if (lane == 0) s_y[wid] = p + wob[wid];
        }
        __syncthreads();
        if (tid < 4 && (b*4 + tid) < out_size) out[b*4 + tid] = s_y[tid];
        if (tid == 0 && out_size >= BB*YY + BB) {
            int am = 0; float bv = s_y[0];
            #pragma unroll
            for (int o = 1; o < 4; o++) if (s_y[o] > bv) { bv = s_y[o]; am = o; }
            out[BB*YY + b] = (float)am;
        }
    }
}

// ---------------- launch ----------------
extern "C" void kernel_launch(void* const* d_in, const int* in_sizes, int n_in,
                              void* d_out, int out_size)
{
    const float* x    = (const float*)d_in[0];
    const float* c1w  = (const float*)d_in[1];
    const float* c1b  = (const float*)d_in[2];
    const float* c2w  = (const float*)d_in[3];
    const float* c2b  = (const float*)d_in[4];
    const float* c3w  = (const float*)d_in[5];
    const float* c3b  = (const float*)d_in[6];
    const float* fc1w = (const float*)d_in[7];
    const float* fc1b = (const float*)d_in[8];
    const float* fc2w = (const float*)d_in[9];
    const float* fc2b = (const float*)d_in[10];
    const float* gamma= (const float*)d_in[11];
    const float* beta = (const float*)d_in[12];
    const float* lwi  = (const float*)d_in[13];
    const float* lwh  = (const float*)d_in[14];
    const float* lb   = (const float*)d_in[15];
    const float* wk   = (const float*)d_in[16];
    const float* wwk  = (const float*)d_in[17];
    const float* wv   = (const float*)d_in[18];
    const float* wo   = (const float*)d_in[19];
    const float* wob  = (const float*)d_in[20];
    const float* mem0 = (const float*)d_in[21];
    float* out = (float*)d_out;

    cudaFuncSetAttribute(k_conv, cudaFuncAttributeMaxDynamicSharedMemorySize,
                         CONV_SMEM_FLOATS * 4);

    float *p_h3, *p_fc1, *p_z, *p_g1, *p_g2, *p_hd1, *p_hd2, *p_h, *p_wcat, *p_whead;
    cudaGetSymbolAddress((void**)&p_h3,    g_h3);
    cudaGetSymbolAddress((void**)&p_fc1,   g_fc1);
    cudaGetSymbolAddress((void**)&p_z,     g_z);
    cudaGetSymbolAddress((void**)&p_g1,    g_gates);
    cudaGetSymbolAddress((void**)&p_g2,    g_gates2);
    cudaGetSymbolAddress((void**)&p_hd1,   g_heads);
    cudaGetSymbolAddress((void**)&p_hd2,   g_heads2);
    cudaGetSymbolAddress((void**)&p_h,     g_hst);
    cudaGetSymbolAddress((void**)&p_wcat,  g_Wcat);
    cudaGetSymbolAddress((void**)&p_whead, g_Whead);

    // setup (memory init, weight concat, out zeroing) — one launch
    k_setup<<<(BB*MEMN*KSZ + 255)/256, 256>>>(mem0, lwi, lwh, wk, wwk, wv, out, out_size);

    // encoder
    k_conv<<<NFRM, 256, CONV_SMEM_FLOATS * 4>>>(x, c1w, c1b, c2w, c2b, c3w, c3b);
    // fc1: [5120,512] @ [256,512]^T -> relu
    k_gemm<<<dim3(4, 80, 1), 256>>>(p_h3, 512, fc1w, 512, fc1b, p_fc1, nullptr, 256, 512, 0, 1, 0, 0);
    // fc2: [5120,256] @ [128,256]^T -> relu
    k_gemm<<<dim3(2, 80, 1), 256>>>(p_fc1, 256, fc2w, 256, fc2b, p_z, nullptr, 128, 256, 0, 1, 0, 0);
    // context norm over time
    k_ctxnorm<<<BB, 128>>>(gamma, beta);

    for (int t = 0; t < TT; t++) {
        // gates: X(gathered [z_t|r|h]) @ Wcat^T + b, split-K x2 via blockIdx.z
        k_gemm<<<dim3(16, 4, 2), 256>>>(nullptr, 0, p_wcat, 640, lb,
                                        p_g1, p_g2, 1024, 320, 320, 0, 1, t);
        k_lstm<<<BB*HH/256, 256>>>();
        // heads: h @ Whead^T (split-K x2)
        k_gemm<<<dim3(12, 4, 2), 256>>>(p_h, 256, p_whead, 256, nullptr,
                                        p_hd1, p_hd2, 768, 128, 128, 0, 0, 0);
        k_mem<<<BB, 256>>>(t, wo, wob, out, out_size);
    }
}